// round 9
// baseline (speedup 1.0000x reference)
#include <cuda_runtime.h>
#include <math.h>

// Problem constants
#define VOCAB 50257
#define EMB   16
#define BS    8
#define MCW   512
#define NTOK  (BS * MCW)      // 4096 tokens

// Scratch (device globals: allocation-free)
__device__ float g_Q[NTOK * EMB];
__device__ float g_K[NTOK * EMB];
__device__ float g_V[NTOK * EMB];
__device__ float g_Wt[BS * MCW * MCW];   // g_Wt[b][k][q] : softmaxed weight (b,q,k), k-major
__device__ float g_out[NTOK * EMB];

// ---------------------------------------------------------------------------
// packed fp32x2 helpers (float2 constraints — proven no-spill form)
// ---------------------------------------------------------------------------
__device__ __forceinline__ float2 fma2(float2 a, float2 b, float2 c) {
    float2 d;
    asm("{\n\t"
        ".reg .b64 ra, rb, rc, rd;\n\t"
        "mov.b64 ra, {%2, %3};\n\t"
        "mov.b64 rb, {%4, %5};\n\t"
        "mov.b64 rc, {%6, %7};\n\t"
        "fma.rn.f32x2 rd, ra, rb, rc;\n\t"
        "mov.b64 {%0, %1}, rd;\n\t"
        "}"
        : "=f"(d.x), "=f"(d.y)
        : "f"(a.x), "f"(a.y), "f"(b.x), "f"(b.y), "f"(c.x), "f"(c.y));
    return d;
}

__device__ __forceinline__ float2 add2(float2 a, float2 b) {
    float2 d;
    asm("{\n\t"
        ".reg .b64 ra, rb, rd;\n\t"
        "mov.b64 ra, {%2, %3};\n\t"
        "mov.b64 rb, {%4, %5};\n\t"
        "add.rn.f32x2 rd, ra, rb;\n\t"
        "mov.b64 {%0, %1}, rd;\n\t"
        "}"
        : "=f"(d.x), "=f"(d.y)
        : "f"(a.x), "f"(a.y), "f"(b.x), "f"(b.y));
    return d;
}

// ---------------------------------------------------------------------------
// Kernel 1: embedding gather + Q/K/V projections
// ---------------------------------------------------------------------------
__global__ void qkv_kernel(const int* __restrict__ x,
                           const float* __restrict__ emb_table,
                           const float* __restrict__ Wq, const float* __restrict__ bq,
                           const float* __restrict__ Wk, const float* __restrict__ bk,
                           const float* __restrict__ Wv, const float* __restrict__ bv) {
    __shared__ float semb[16][EMB];
    int lt = threadIdx.x >> 4;
    int e  = threadIdx.x & 15;
    int tok = blockIdx.x * 16 + lt;
    int id = x[tok];
    semb[lt][e] = emb_table[id * EMB + e];
    __syncthreads();

    float q = bq[e], k = bk[e], v = bv[e];
#pragma unroll
    for (int j = 0; j < EMB; ++j) {
        float ej = semb[lt][j];
        q = fmaf(Wq[e * EMB + j], ej, q);
        k = fmaf(Wk[e * EMB + j], ej, k);
        v = fmaf(Wv[e * EMB + j], ej, v);
    }
    g_Q[tok * EMB + e] = q;
    g_K[tok * EMB + e] = k;
    g_V[tok * EMB + e] = v;
}

// ---------------------------------------------------------------------------
// Kernel 2: scores + mask + zero->-inf quirk + softmax over QUERY axis
// grid: (MCW/8, BS); block: 512 threads (q). writes g_Wt[b][k][q]
// Batched reductions: all 8 k-columns reduced together -> 4 syncthreads total
// (previous version: 16 block_reduce calls = 48 syncthreads).
// ---------------------------------------------------------------------------
__global__ void attn_weights_kernel() {
    int kc0  = blockIdx.x * 8;
    int b    = blockIdx.y;
    int tid  = threadIdx.x;   // q index
    int wid  = tid >> 5;
    int lane = tid & 31;

    __shared__ float sK[8][EMB];
    __shared__ float sredM[16][8];
    __shared__ float sredS[16][8];
    __shared__ float sfinM[8];
    __shared__ float sfinS[8];

    const float4* qrow = reinterpret_cast<const float4*>(g_Q + (b * MCW + tid) * EMB);
    float4 q0 = qrow[0], q1 = qrow[1], q2 = qrow[2], q3 = qrow[3];

    if (tid < 8 * EMB) {
        sK[tid >> 4][tid & 15] = g_K[(b * MCW + kc0 + (tid >> 4)) * EMB + (tid & 15)];
    }
    __syncthreads();

    float val[8];
#pragma unroll
    for (int kc = 0; kc < 8; ++kc) {
        const float* kv = sK[kc];
        float s = 0.0f;
        s = fmaf(q0.x, kv[0],  s); s = fmaf(q0.y, kv[1],  s);
        s = fmaf(q0.z, kv[2],  s); s = fmaf(q0.w, kv[3],  s);
        s = fmaf(q1.x, kv[4],  s); s = fmaf(q1.y, kv[5],  s);
        s = fmaf(q1.z, kv[6],  s); s = fmaf(q1.w, kv[7],  s);
        s = fmaf(q2.x, kv[8],  s); s = fmaf(q2.y, kv[9],  s);
        s = fmaf(q2.z, kv[10], s); s = fmaf(q2.w, kv[11], s);
        s = fmaf(q3.x, kv[12], s); s = fmaf(q3.y, kv[13], s);
        s = fmaf(q3.z, kv[14], s); s = fmaf(q3.w, kv[15], s);
        // mask: keep only k <= q ; quirk: exact-zero scores -> -inf
        val[kc] = ((kc0 + kc) <= tid && s != 0.0f) ? s : -INFINITY;
    }

    // --- batched max reduction over q (512) for all 8 columns ---
#pragma unroll
    for (int kc = 0; kc < 8; ++kc) {
        float v = val[kc];
#pragma unroll
        for (int o = 16; o > 0; o >>= 1) v = fmaxf(v, __shfl_xor_sync(0xffffffffu, v, o));
        if (lane == 0) sredM[wid][kc] = v;
    }
    __syncthreads();
    if (tid < 8) {
        float m = -INFINITY;
#pragma unroll
        for (int w = 0; w < 16; ++w) m = fmaxf(m, sredM[w][tid]);
        sfinM[tid] = m;
    }
    __syncthreads();

    // --- exp + batched sum reduction ---
    float p[8];
#pragma unroll
    for (int kc = 0; kc < 8; ++kc) {
        p[kc] = __expf(val[kc] - sfinM[kc]);
        float v = p[kc];
#pragma unroll
        for (int o = 16; o > 0; o >>= 1) v += __shfl_xor_sync(0xffffffffu, v, o);
        if (lane == 0) sredS[wid][kc] = v;
    }
    __syncthreads();
    if (tid < 8) {
        float s = 0.0f;
#pragma unroll
        for (int w = 0; w < 16; ++w) s += sredS[w][tid];
        sfinS[tid] = s;
    }
    __syncthreads();

#pragma unroll
    for (int kc = 0; kc < 8; ++kc) {
        float w = p[kc] / sfinS[kc];
        g_Wt[((size_t)(b * MCW + kc0 + kc)) * MCW + tid] = w;   // coalesced over q
    }
}

// ---------------------------------------------------------------------------
// Kernel 3: out[b,w,e] = sum_p Wt[b][p][w] * V[b,p,e]
// ---------------------------------------------------------------------------
__global__ void attn_out_kernel() {
    int b  = blockIdx.y;
    int w  = blockIdx.x * 16 + (threadIdx.x & 15);
    int e  = threadIdx.x >> 4;

    __shared__ float sV[MCW * EMB];
    const float* Vb = g_V + b * MCW * EMB;
    for (int i = threadIdx.x; i < MCW * EMB; i += 256) sV[i] = Vb[i];
    __syncthreads();

    const float* Wtb = g_Wt + (size_t)b * MCW * MCW;
    float acc = 0.0f;
#pragma unroll 8
    for (int p = 0; p < MCW; ++p)
        acc = fmaf(Wtb[p * MCW + w], sV[p * EMB + e], acc);

    g_out[(b * MCW + w) * EMB + e] = acc;
}

// ---------------------------------------------------------------------------
// Kernel 4: logits[t, v] = dot(out[t,:], Wl[v,:]) + bl[v]
// 2 vocab rows per thread (wl = 32 regs) -> target 64 regs, 4 blocks/SM,
// 32 warps = 2x the warps of the 4-row version. Dup-quad smem staging as R7.
// Thread owns rows {v, v+256}, v = vbase+tid -> lane-consecutive STG.32.
// ---------------------------------------------------------------------------
#define TC  256      // tokens per block
#define VB  512      // vocab rows per block (256 threads * 2 rows)

__global__ void __launch_bounds__(256, 4)
logits_kernel(const float* __restrict__ Wl, const float* __restrict__ bl,
              float* __restrict__ logits) {
    __shared__ float4 stok[TC * 8];   // 32 KB : stok[t*8+j] = (t[2j],t[2j],t[2j+1],t[2j+1])

    int tid   = threadIdx.x;
    int t0    = blockIdx.y * TC;
    int vbase = blockIdx.x * VB;

    // stage dup-quad token vectors
    const float2* src = reinterpret_cast<const float2*>(g_out + t0 * EMB);
    for (int i = tid; i < TC * 8; i += 256) {
        float2 v = src[i];
        stok[i] = make_float4(v.x, v.x, v.y, v.y);
    }

    // this thread's 2 vocab rows (lane-consecutive stores)
    int v0 = vbase + tid;
    int v1 = v0 + 256;
    bool a0 = (v0 < VOCAB), a1 = (v1 < VOCAB);

    float2 wl[EMB];
#pragma unroll
    for (int k = 0; k < EMB; ++k) {
        wl[k] = make_float2(a0 ? Wl[v0 * EMB + k] : 0.0f,
                            a1 ? Wl[v1 * EMB + k] : 0.0f);
    }
    float2 bias = make_float2(a0 ? bl[v0] : 0.0f, a1 ? bl[v1] : 0.0f);

    __syncthreads();

    for (int t = 0; t < TC; ++t) {
        const float4* tk = stok + t * 8;
        // 2 independent chains, depth 8
        float2 p0 = bias;
        float2 p1 = make_float2(0.0f, 0.0f);
#pragma unroll
        for (int j = 0; j < 8; ++j) {
            float4 tv = tk[j];
            p0 = fma2(wl[2 * j],     make_float2(tv.x, tv.y), p0);
            p1 = fma2(wl[2 * j + 1], make_float2(tv.z, tv.w), p1);
        }
        float2 acc = add2(p0, p1);     // (logit[v0], logit[v1])

        size_t base = (size_t)(t0 + t) * VOCAB;
        if (a0) logits[base + v0] = acc.x;
        if (a1) logits[base + v1] = acc.y;
    }
}

// ---------------------------------------------------------------------------
extern "C" void kernel_launch(void* const* d_in, const int* in_sizes, int n_in,
                              void* d_out, int out_size) {
    const int*   x         = (const int*)  d_in[0];
    const float* emb_table = (const float*)d_in[1];
    const float* Wq        = (const float*)d_in[2];
    const float* bq        = (const float*)d_in[3];
    const float* Wk        = (const float*)d_in[4];
    const float* bk        = (const float*)d_in[5];
    const float* Wv        = (const float*)d_in[6];
    const float* bv        = (const float*)d_in[7];
    const float* Wl        = (const float*)d_in[8];
    const float* bl        = (const float*)d_in[9];
    float* logits          = (float*)d_out;

    qkv_kernel<<<NTOK / 16, 256>>>(x, emb_table, Wq, bq, Wk, bk, Wv, bv);

    dim3 g2(MCW / 8, BS);
    attn_weights_kernel<<<g2, MCW>>>();

    dim3 g3(MCW / 16, BS);
    attn_out_kernel<<<g3, 256>>>();

    dim3 g4((VOCAB + VB - 1) / VB, NTOK / TC);
    logits_kernel<<<g4, 256>>>(Wl, bl, logits);
}